// round 1
// baseline (speedup 1.0000x reference)
#include <cuda_runtime.h>

#define C_DIM 256
#define N_TOK 8
#define D_DIM 512
#define HW    4096
#define B_SZ  4
#define TILE_P 32
#define EPS 1e-6f

// persistent scratch (no runtime allocation allowed)
__device__ float g_sg[B_SZ * C_DIM];          // per-batch folded query vector
__device__ float g_wovgT[C_DIM * C_DIM];      // [ch][co]  (Wo @ Wv, g folded, transposed)

// ---------------------------------------------------------------------------
// sg[b,ch] = g[ch] * D^{-1/2} * sum_d Wk[d,ch] * (Wq q_b)[d]
// ---------------------------------------------------------------------------
__global__ void k_sg(const float* __restrict__ q, const float* __restrict__ Wq,
                     const float* __restrict__ Wkv, const float* __restrict__ g) {
    int b = blockIdx.x;
    __shared__ float qs[C_DIM];
    __shared__ float qps[D_DIM];
    int tid = threadIdx.x;
    qs[tid] = q[b * C_DIM + tid];
    __syncthreads();
    int warp = tid >> 5, lane = tid & 31;
    for (int d = warp; d < D_DIM; d += 8) {
        float s = 0.f;
        for (int cc = lane; cc < C_DIM; cc += 32) s += Wq[d * C_DIM + cc] * qs[cc];
        #pragma unroll
        for (int o = 16; o > 0; o >>= 1) s += __shfl_xor_sync(0xffffffffu, s, o);
        if (lane == 0) qps[d] = s;
    }
    __syncthreads();
    float acc = 0.f;
    for (int d = 0; d < D_DIM; ++d) acc += Wkv[d * C_DIM + tid] * qps[d];
    g_sg[b * C_DIM + tid] = acc * g[tid] * rsqrtf((float)D_DIM);
}

// ---------------------------------------------------------------------------
// WovgT[ch][co] = g[ch] * sum_d Wo[co,d] * Wv[d,ch]   (Wv = rows D..2D-1 of Wkv)
// 64 blocks, each computes 4 co rows; Wo rows staged in smem; Wv streamed coalesced.
// ---------------------------------------------------------------------------
__global__ void k_wov(const float* __restrict__ Wo, const float* __restrict__ Wkv,
                      const float* __restrict__ g) {
    int co0 = blockIdx.x * 4;
    __shared__ float wo_s[4][D_DIM];
    int tid = threadIdx.x;
    for (int i = tid; i < 4 * D_DIM; i += 256) wo_s[i >> 9][i & 511] = Wo[co0 * D_DIM + i];
    __syncthreads();
    const float* wv = Wkv + (size_t)D_DIM * C_DIM;  // v half
    float a0 = 0.f, a1 = 0.f, a2 = 0.f, a3 = 0.f;
    #pragma unroll 4
    for (int d = 0; d < D_DIM; ++d) {
        float v = __ldg(wv + (size_t)d * C_DIM + tid);
        a0 += wo_s[0][d] * v; a1 += wo_s[1][d] * v;
        a2 += wo_s[2][d] * v; a3 += wo_s[3][d] * v;
    }
    float gg = g[tid];
    g_wovgT[tid * C_DIM + co0 + 0] = a0 * gg;
    g_wovgT[tid * C_DIM + co0 + 1] = a1 * gg;
    g_wovgT[tid * C_DIM + co0 + 2] = a2 * gg;
    g_wovgT[tid * C_DIM + co0 + 3] = a3 * gg;
}

// ---------------------------------------------------------------------------
// Fused main kernel: one block = 32 contiguous pixels of one batch.
//   Phase A: per (n,pixel) RMS sum-of-squares + dot with sg -> softmax weights w_n*inv_n
//   Phase B: agg[ch][p] = sum_n w_n * c[b,n,ch,p]   (re-reads c, descending ch for L2)
//   Phase C: out[co][p] = bo[co] + sum_ch WovgT[ch][co] * agg[ch][p]  (8x4 reg tile)
// ---------------------------------------------------------------------------
__global__ void __launch_bounds__(256) k_main(const float* __restrict__ c,
                                              const float* __restrict__ bo,
                                              float* __restrict__ out) {
    __shared__ float agg[C_DIM][TILE_P + 4];
    __shared__ float sm_dot[N_TOK][TILE_P];
    __shared__ float w_s[N_TOK][TILE_P];
    __shared__ float sg_s[C_DIM];

    int tid = threadIdx.x;
    int blk = blockIdx.x;
    int b = blk >> 7;                    // 128 blocks per batch
    int p0 = (blk & 127) * TILE_P;

    sg_s[tid] = g_sg[b * C_DIM + tid];
    __syncthreads();

    const float* cb = c + (size_t)b * N_TOK * C_DIM * HW;

    // ---- Phase A: weights ----
    {
        int n = tid >> 5, pl = tid & 31;     // warp n, lane = pixel
        const float* row = cb + (size_t)n * C_DIM * HW + p0 + pl;
        float ss = 0.f, dt = 0.f;
        #pragma unroll 4
        for (int ch = 0; ch < C_DIM; ++ch) {
            float v = __ldg(row + (size_t)ch * HW);
            ss += v * v;
            dt += v * sg_s[ch];
        }
        float inv = rsqrtf(ss * (1.0f / C_DIM) + EPS);
        sm_dot[n][pl] = dt * inv;
        __syncthreads();
        float m = sm_dot[0][pl];
        #pragma unroll
        for (int i = 1; i < N_TOK; ++i) m = fmaxf(m, sm_dot[i][pl]);
        float sum = 0.f;
        #pragma unroll
        for (int i = 0; i < N_TOK; ++i) sum += __expf(sm_dot[i][pl] - m);
        float e = __expf(sm_dot[n][pl] - m);
        w_s[n][pl] = e / sum * inv;
    }
    __syncthreads();

    // ---- Phase B: agg build (float4 over pixels, descending ch for L2 reuse) ----
    {
        int warp = tid >> 5, lane = tid & 31;
        int cho = lane >> 3;                 // 0..3 : ch offset within warp
        int pfl = (lane & 7) * 4;            // pixel*4 within tile
        float4 wv4[N_TOK];
        #pragma unroll
        for (int i = 0; i < N_TOK; ++i) wv4[i] = *(const float4*)&w_s[i][pfl];
        const float4* cb4 = (const float4*)cb;
        int pb4 = (p0 >> 2) + (pfl >> 2);
        for (int chs = 7; chs >= 0; --chs) {
            int ch = chs * 32 + warp * 4 + cho;
            float4 a = make_float4(0.f, 0.f, 0.f, 0.f);
            #pragma unroll
            for (int i = 0; i < N_TOK; ++i) {
                float4 v = __ldg(cb4 + (size_t)(i * C_DIM + ch) * (HW / 4) + pb4);
                a.x += wv4[i].x * v.x; a.y += wv4[i].y * v.y;
                a.z += wv4[i].z * v.z; a.w += wv4[i].w * v.w;
            }
            *(float4*)&agg[ch][pfl] = a;
        }
    }
    __syncthreads();

    // ---- Phase C: epilogue GEMM, 8 co x 4 p per thread ----
    {
        float acc[8][4];
        #pragma unroll
        for (int i = 0; i < 8; ++i)
            #pragma unroll
            for (int j = 0; j < 4; ++j) acc[i][j] = 0.f;

        int pp = (tid & 7) * 4;
        int co0 = (tid >> 3) * 8;
        #pragma unroll 4
        for (int ch = 0; ch < C_DIM; ++ch) {
            float4 a  = *(const float4*)&agg[ch][pp];
            float4 w0 = __ldg((const float4*)&g_wovgT[ch * C_DIM + co0]);
            float4 w1 = __ldg((const float4*)&g_wovgT[ch * C_DIM + co0 + 4]);
            acc[0][0] += w0.x * a.x; acc[0][1] += w0.x * a.y; acc[0][2] += w0.x * a.z; acc[0][3] += w0.x * a.w;
            acc[1][0] += w0.y * a.x; acc[1][1] += w0.y * a.y; acc[1][2] += w0.y * a.z; acc[1][3] += w0.y * a.w;
            acc[2][0] += w0.z * a.x; acc[2][1] += w0.z * a.y; acc[2][2] += w0.z * a.z; acc[2][3] += w0.z * a.w;
            acc[3][0] += w0.w * a.x; acc[3][1] += w0.w * a.y; acc[3][2] += w0.w * a.z; acc[3][3] += w0.w * a.w;
            acc[4][0] += w1.x * a.x; acc[4][1] += w1.x * a.y; acc[4][2] += w1.x * a.z; acc[4][3] += w1.x * a.w;
            acc[5][0] += w1.y * a.x; acc[5][1] += w1.y * a.y; acc[5][2] += w1.y * a.z; acc[5][3] += w1.y * a.w;
            acc[6][0] += w1.z * a.x; acc[6][1] += w1.z * a.y; acc[6][2] += w1.z * a.z; acc[6][3] += w1.z * a.w;
            acc[7][0] += w1.w * a.x; acc[7][1] += w1.w * a.y; acc[7][2] += w1.w * a.z; acc[7][3] += w1.w * a.w;
        }

        float* ob = out + (size_t)b * C_DIM * HW + p0 + pp;
        #pragma unroll
        for (int i = 0; i < 8; ++i) {
            float bb = bo[co0 + i];
            float4 r = make_float4(acc[i][0] + bb, acc[i][1] + bb,
                                   acc[i][2] + bb, acc[i][3] + bb);
            *(float4*)(ob + (size_t)(co0 + i) * HW) = r;
        }
    }
}

extern "C" void kernel_launch(void* const* d_in, const int* in_sizes, int n_in,
                              void* d_out, int out_size) {
    const float* q   = (const float*)d_in[0];
    const float* c   = (const float*)d_in[1];
    const float* g   = (const float*)d_in[2];
    const float* Wq  = (const float*)d_in[3];
    const float* Wkv = (const float*)d_in[4];
    const float* Wo  = (const float*)d_in[5];
    const float* bo  = (const float*)d_in[6];
    float* out = (float*)d_out;

    k_sg<<<B_SZ, 256>>>(q, Wq, Wkv, g);
    k_wov<<<64, 256>>>(Wo, Wkv, g);
    k_main<<<B_SZ * (HW / TILE_P), 256>>>(c, bo, out);
}

// round 3
// speedup vs baseline: 1.0093x; 1.0093x over previous
#include <cuda_runtime.h>
#include <cstdint>

#define C_DIM 256
#define N_TOK 8
#define D_DIM 512
#define HW    4096
#define B_SZ  4
#define EPS   1e-6f

// ---- persistent scratch (no runtime allocation allowed) ----
__device__ float g_qp[B_SZ * D_DIM];            // Wq @ q_b
__device__ float g_sgp[8][B_SZ * C_DIM];        // partial sg over d-chunks
__device__ float g_sg[B_SZ * C_DIM];            // folded query vector
__device__ float g_wovgT[C_DIM * C_DIM];        // [ch][co] = g[ch]*sum_d Wo[co,d]*Wv[d,ch]
__device__ float g_agg[(size_t)B_SZ * C_DIM * HW];  // 16MB aggregation buffer

// f32x2 packed FMA (FFMA2) — ptxas never emits this from C++
#define FMA2(d, a, b, c) \
    asm("fma.rn.f32x2 %0, %1, %2, %3;" : "=l"(d) : "l"(a), "l"(b), "l"(c))

// ---------------------------------------------------------------------------
// qp[b,d] = sum_c Wq[d,c] * q[b,c]
// ---------------------------------------------------------------------------
__global__ void k_qp(const float* __restrict__ q, const float* __restrict__ Wq) {
    int b = blockIdx.x;
    __shared__ float qs[C_DIM];
    int tid = threadIdx.x, warp = tid >> 5, lane = tid & 31;
    qs[tid] = q[b * C_DIM + tid];
    __syncthreads();
    for (int d = warp; d < D_DIM; d += 8) {
        float s = 0.f;
        #pragma unroll
        for (int cc = lane; cc < C_DIM; cc += 32) s += Wq[d * C_DIM + cc] * qs[cc];
        #pragma unroll
        for (int o = 16; o > 0; o >>= 1) s += __shfl_xor_sync(0xffffffffu, s, o);
        if (lane == 0) g_qp[b * D_DIM + d] = s;
    }
}

// ---------------------------------------------------------------------------
// sgp[ck][b,ch] = sum_{d in chunk ck} Wk[d,ch] * qp[b,d]   (32 blocks)
// ---------------------------------------------------------------------------
__global__ void k_sgp(const float* __restrict__ Wkv) {
    int b = blockIdx.x, ck = blockIdx.y, tid = threadIdx.x;
    __shared__ float qps[64];
    if (tid < 64) qps[tid] = g_qp[b * D_DIM + ck * 64 + tid];
    __syncthreads();
    float a = 0.f;
    const float* wk = Wkv + (size_t)(ck * 64) * C_DIM + tid;
    #pragma unroll 8
    for (int d = 0; d < 64; ++d) a += wk[(size_t)d * C_DIM] * qps[d];
    g_sgp[ck][b * C_DIM + tid] = a;
}

// ---------------------------------------------------------------------------
// sg[b,ch] = g[ch] * D^{-1/2} * sum_ck sgp[ck][b,ch]
// ---------------------------------------------------------------------------
__global__ void k_sgr(const float* __restrict__ g) {
    int b = blockIdx.x, tid = threadIdx.x;
    float s = 0.f;
    #pragma unroll
    for (int i = 0; i < 8; ++i) s += g_sgp[i][b * C_DIM + tid];
    g_sg[b * C_DIM + tid] = s * g[tid] * rsqrtf((float)D_DIM);
}

// ---------------------------------------------------------------------------
// WovgT[ch][co] = g[ch] * sum_d Wo[co,d] * Wv[d,ch]
// ---------------------------------------------------------------------------
__global__ void k_wov(const float* __restrict__ Wo, const float* __restrict__ Wkv,
                      const float* __restrict__ g) {
    int co0 = blockIdx.x * 4;
    __shared__ float wo_s[4][D_DIM];
    int tid = threadIdx.x;
    for (int i = tid; i < 4 * D_DIM; i += 256) wo_s[i >> 9][i & 511] = Wo[co0 * D_DIM + i];
    __syncthreads();
    const float* wv = Wkv + (size_t)D_DIM * C_DIM;
    float a0 = 0.f, a1 = 0.f, a2 = 0.f, a3 = 0.f;
    #pragma unroll 8
    for (int d = 0; d < D_DIM; ++d) {
        float v = __ldg(wv + (size_t)d * C_DIM + tid);
        a0 += wo_s[0][d] * v; a1 += wo_s[1][d] * v;
        a2 += wo_s[2][d] * v; a3 += wo_s[3][d] * v;
    }
    float gg = g[tid];
    g_wovgT[tid * C_DIM + co0 + 0] = a0 * gg;
    g_wovgT[tid * C_DIM + co0 + 1] = a1 * gg;
    g_wovgT[tid * C_DIM + co0 + 2] = a2 * gg;
    g_wovgT[tid * C_DIM + co0 + 3] = a3 * gg;
}

// ---------------------------------------------------------------------------
// k_fuse: single pass over c. One block = 8 pixels of one batch.
//   Stage tile in smem, compute RMS+dot+softmax, aggregate, write agg to gmem.
// smem: cs[2048 rows][12] (8 p + 4 pad, float4-aligned) + small arrays
// ---------------------------------------------------------------------------
#define FUSE_SMEM (2048 * 12 * 4 + (64 * 3 + 256) * 4)
__global__ void __launch_bounds__(256, 2) k_fuse(const float* __restrict__ c) {
    extern __shared__ float sh[];
    float* cs   = sh;                 // [ (n*256+ch) * 12 + p ]
    float* dots = sh + 2048 * 12;     // [64] = [n*8+p]
    float* invs = dots + 64;
    float* wgt  = invs + 64;
    float* sg_s = wgt + 64;           // [256]

    int tid = threadIdx.x;
    int blk = blockIdx.x;
    int b = blk >> 9;
    int p0 = (blk & 511) * 8;

    sg_s[tid] = g_sg[b * C_DIM + tid];
    const float* cb = c + (size_t)b * N_TOK * C_DIM * HW;

    // ---- load tile: 2048 rows x 8 floats (2 float4 each) ----
    #pragma unroll
    for (int k = 0; k < 16; ++k) {
        int idx = tid + k * 256;
        int row = idx >> 1, f = idx & 1;
        float4 v = __ldg((const float4*)(cb + (size_t)row * HW + p0) + f);
        *(float4*)(cs + row * 12 + f * 4) = v;
    }
    __syncthreads();

    // ---- phase A: per (n,p) RMS + dot, 4 threads per pair ----
    {
        int sub = tid & 3, pair = tid >> 2;       // pair = n*8+p
        int n = pair >> 3, p = pair & 7;
        float ss = 0.f, dt = 0.f;
        #pragma unroll 8
        for (int ch = sub; ch < C_DIM; ch += 4) {
            float v = cs[(n * C_DIM + ch) * 12 + p];
            ss += v * v;
            dt += v * sg_s[ch];
        }
        ss += __shfl_xor_sync(0xffffffffu, ss, 1);
        dt += __shfl_xor_sync(0xffffffffu, dt, 1);
        ss += __shfl_xor_sync(0xffffffffu, ss, 2);
        dt += __shfl_xor_sync(0xffffffffu, dt, 2);
        if (sub == 0) {
            float inv = rsqrtf(ss * (1.0f / C_DIM) + EPS);
            dots[pair] = dt * inv;
            invs[pair] = inv;
        }
    }
    __syncthreads();
    if (tid < 64) {
        int pp = tid & 7;
        float m = dots[pp];
        #pragma unroll
        for (int i = 1; i < N_TOK; ++i) m = fmaxf(m, dots[i * 8 + pp]);
        float sum = 0.f;
        #pragma unroll
        for (int i = 0; i < N_TOK; ++i) sum += __expf(dots[i * 8 + pp] - m);
        wgt[tid] = __expf(dots[tid] - m) / sum * invs[tid];
    }
    __syncthreads();

    // ---- phase B: thread = ch; agg[ch][p] = sum_n w[n][p]*cs[n][ch][p] ----
    {
        float4 a0 = make_float4(0.f, 0.f, 0.f, 0.f);
        float4 a1 = make_float4(0.f, 0.f, 0.f, 0.f);
        #pragma unroll
        for (int i = 0; i < N_TOK; ++i) {
            const float* r = cs + (i * C_DIM + tid) * 12;
            float4 v0 = *(const float4*)r;
            float4 v1 = *(const float4*)(r + 4);
            const float* w = wgt + i * 8;
            a0.x += w[0] * v0.x; a0.y += w[1] * v0.y; a0.z += w[2] * v0.z; a0.w += w[3] * v0.w;
            a1.x += w[4] * v1.x; a1.y += w[5] * v1.y; a1.z += w[6] * v1.z; a1.w += w[7] * v1.w;
        }
        float* ag = g_agg + (size_t)(b * C_DIM + tid) * HW + p0;
        *(float4*)ag = a0;
        *(float4*)(ag + 4) = a1;
    }
}

// ---------------------------------------------------------------------------
// k_gemm: out[b][co][p] = bo[co] + sum_ch WovgT[ch][co] * agg[b][ch][p]
// Tiles: 64 co x 128 p per block, K-chunks of 32, FFMA2 inner loop.
// ---------------------------------------------------------------------------
#define TP  128
#define TCO 64
#define KC  32
__global__ void __launch_bounds__(256) k_gemm(const float* __restrict__ bo,
                                              float* __restrict__ out) {
    __shared__ float aggS[KC][TP];                       // 16KB
    __shared__ unsigned long long wovD[KC][TCO];         // 16KB, (w,w) pairs
    int tid = threadIdx.x;
    int blk = blockIdx.x;                  // 4b * 4ct * 32pt = 512
    int pt = blk & 31, ct = (blk >> 5) & 3, b = blk >> 7;
    int p0 = pt * TP, co0 = ct * TCO;
    int tx = tid & 31, ty = tid >> 5;      // 32 p-cols x 8 co-rows
    int po = tx * 4, coo = ty * 8;

    unsigned long long acc[8][2];
    #pragma unroll
    for (int i = 0; i < 8; ++i) { acc[i][0] = 0ull; acc[i][1] = 0ull; }

    const float* aggB = g_agg + (size_t)b * C_DIM * HW + p0;

    for (int ch0 = 0; ch0 < C_DIM; ch0 += KC) {
        __syncthreads();
        // stage agg chunk [32ch][128p]
        #pragma unroll
        for (int k = 0; k < 4; ++k) {
            int idx = tid + k * 256;
            int ch = idx >> 5, f = idx & 31;
            *(float4*)&aggS[ch][f * 4] =
                __ldg((const float4*)(aggB + (size_t)(ch0 + ch) * HW) + f);
        }
        // stage weights, pre-duplicated into f32x2 pairs
        #pragma unroll
        for (int k = 0; k < 8; ++k) {
            int idx = tid + k * 256;
            int ch = idx >> 6, co = idx & 63;
            float w = __ldg(&g_wovgT[(ch0 + ch) * C_DIM + co0 + co]);
            unsigned long long pk;
            asm("mov.b64 %0, {%1, %1};" : "=l"(pk) : "r"(__float_as_uint(w)));
            wovD[ch][co] = pk;
        }
        __syncthreads();
        #pragma unroll
        for (int ch = 0; ch < KC; ++ch) {
            ulonglong2 ap = *(const ulonglong2*)&aggS[ch][po];   // 2 f32x2 pairs
            const unsigned long long* wp = &wovD[ch][coo];
            #pragma unroll
            for (int i = 0; i < 8; ++i) {
                FMA2(acc[i][0], wp[i], ap.x, acc[i][0]);
                FMA2(acc[i][1], wp[i], ap.y, acc[i][1]);
            }
        }
    }

    // output base: batch + co-tile + pixel offsets (R2 bug: co0 was missing)
    float* ob = out + ((size_t)b * C_DIM + co0 + coo) * HW + p0 + po;
    #pragma unroll
    for (int i = 0; i < 8; ++i) {
        float bb = __ldg(&bo[co0 + coo + i]);
        unsigned lx, ly, hx, hy;
        asm("mov.b64 {%0, %1}, %2;" : "=r"(lx), "=r"(ly) : "l"(acc[i][0]));
        asm("mov.b64 {%0, %1}, %2;" : "=r"(hx), "=r"(hy) : "l"(acc[i][1]));
        float4 r = make_float4(__uint_as_float(lx) + bb, __uint_as_float(ly) + bb,
                               __uint_as_float(hx) + bb, __uint_as_float(hy) + bb);
        *(float4*)(ob + (size_t)i * HW) = r;
    }
}

extern "C" void kernel_launch(void* const* d_in, const int* in_sizes, int n_in,
                              void* d_out, int out_size) {
    const float* q   = (const float*)d_in[0];
    const float* c   = (const float*)d_in[1];
    const float* g   = (const float*)d_in[2];
    const float* Wq  = (const float*)d_in[3];
    const float* Wkv = (const float*)d_in[4];
    const float* Wo  = (const float*)d_in[5];
    const float* bo  = (const float*)d_in[6];
    float* out = (float*)d_out;

    cudaFuncSetAttribute(k_fuse, cudaFuncAttributeMaxDynamicSharedMemorySize, FUSE_SMEM);

    k_qp<<<B_SZ, 256>>>(q, Wq);
    k_sgp<<<dim3(B_SZ, 8), 256>>>(Wkv);
    k_sgr<<<B_SZ, 256>>>(g);
    k_wov<<<64, 256>>>(Wo, Wkv, g);
    k_fuse<<<B_SZ * (HW / 8), 256, FUSE_SMEM>>>(c);
    k_gemm<<<512, 256>>>(bo, out);
}

// round 4
// speedup vs baseline: 1.4898x; 1.4761x over previous
#include <cuda_runtime.h>
#include <cstdint>

#define C_DIM 256
#define N_TOK 8
#define D_DIM 512
#define HW    4096
#define B_SZ  4
#define EPS   1e-6f

// ---- persistent scratch (no runtime allocation allowed) ----
__device__ float g_qp[B_SZ * D_DIM];                 // Wq @ q_b
__device__ float g_sgp[8][B_SZ * C_DIM];             // partial sg over d-chunks
__device__ float g_sg[B_SZ * C_DIM];                 // folded query vector
__device__ float g_wovp[8][C_DIM * C_DIM];           // partial WovT over d-chunks (2MB)
__device__ float g_wovgT[C_DIM * C_DIM];             // [ch][co]
__device__ float g_agg[(size_t)B_SZ * C_DIM * HW];   // 16MB aggregation buffer

// f32x2 packed FMA (FFMA2) — ptxas never emits this from C++
#define FMA2(d, a, b, c) \
    asm("fma.rn.f32x2 %0, %1, %2, %3;" : "=l"(d) : "l"(a), "l"(b), "l"(c))

// ---------------------------------------------------------------------------
// qp[b,d] = sum_c Wq[d,c] * q[b,c]     grid (B, 8 d-chunks), warp per d-row
// ---------------------------------------------------------------------------
__global__ void k_qp(const float* __restrict__ q, const float* __restrict__ Wq) {
    int b = blockIdx.x, dc = blockIdx.y;
    __shared__ float qs[C_DIM];
    int tid = threadIdx.x, warp = tid >> 5, lane = tid & 31;
    qs[tid] = q[b * C_DIM + tid];
    __syncthreads();
    #pragma unroll
    for (int i = 0; i < 8; ++i) {
        int d = dc * 64 + i * 8 + warp;
        float s = 0.f;
        #pragma unroll
        for (int k = 0; k < 8; ++k) s += __ldg(&Wq[d * C_DIM + lane + k * 32]) * qs[lane + k * 32];
        #pragma unroll
        for (int o = 16; o > 0; o >>= 1) s += __shfl_xor_sync(0xffffffffu, s, o);
        if (lane == 0) g_qp[b * D_DIM + d] = s;
    }
}

// ---------------------------------------------------------------------------
// sgp[ck][b,ch] = sum_{d in 64-chunk ck} Wk[d,ch] * qp[b,d]
// ---------------------------------------------------------------------------
__global__ void k_sgp(const float* __restrict__ Wkv) {
    int b = blockIdx.x, ck = blockIdx.y, tid = threadIdx.x;
    __shared__ float qps[64];
    if (tid < 64) qps[tid] = g_qp[b * D_DIM + ck * 64 + tid];
    __syncthreads();
    float a = 0.f;
    const float* wk = Wkv + (size_t)(ck * 64) * C_DIM + tid;
    #pragma unroll 8
    for (int d = 0; d < 64; ++d) a += __ldg(wk + (size_t)d * C_DIM) * qps[d];
    g_sgp[ck][b * C_DIM + tid] = a;
}

// ---------------------------------------------------------------------------
// sg[b,ch] = g[ch] * D^{-1/2} * sum_ck sgp[ck][b,ch]
// ---------------------------------------------------------------------------
__global__ void k_sgr(const float* __restrict__ g) {
    int b = blockIdx.x, tid = threadIdx.x;
    float s = 0.f;
    #pragma unroll
    for (int i = 0; i < 8; ++i) s += g_sgp[i][b * C_DIM + tid];
    g_sg[b * C_DIM + tid] = s * g[tid] * rsqrtf((float)D_DIM);
}

// ---------------------------------------------------------------------------
// wovp[kc][ch][co] = sum_{d in 64-chunk kc} Wo[co,d] * Wv[d,ch]
// grid (64 co-tiles x 8 k-chunks); thread = ch, 4 co per block
// ---------------------------------------------------------------------------
__global__ void k_wovp(const float* __restrict__ Wo, const float* __restrict__ Wkv) {
    int co0 = blockIdx.x * 4, kc = blockIdx.y;
    __shared__ float wo_s[4][64];
    int tid = threadIdx.x;
    {   // stage Wo[co0..co0+3][kc*64 .. +63]
        int r = tid >> 6, cc = tid & 63;
        wo_s[r][cc] = __ldg(&Wo[(co0 + r) * D_DIM + kc * 64 + cc]);
    }
    __syncthreads();
    const float* wv = Wkv + (size_t)(D_DIM + kc * 64) * C_DIM + tid;
    float a0 = 0.f, a1 = 0.f, a2 = 0.f, a3 = 0.f;
    #pragma unroll 8
    for (int d = 0; d < 64; ++d) {
        float v = __ldg(wv + (size_t)d * C_DIM);
        a0 += wo_s[0][d] * v; a1 += wo_s[1][d] * v;
        a2 += wo_s[2][d] * v; a3 += wo_s[3][d] * v;
    }
    float* o = &g_wovp[kc][tid * C_DIM + co0];
    o[0] = a0; o[1] = a1; o[2] = a2; o[3] = a3;
}

// ---------------------------------------------------------------------------
// wovgT[ch][co] = g[ch] * sum_kc wovp[kc][ch][co]      grid 256
// ---------------------------------------------------------------------------
__global__ void k_wovr(const float* __restrict__ g) {
    int idx = blockIdx.x * 256 + threadIdx.x;
    float s = 0.f;
    #pragma unroll
    for (int i = 0; i < 8; ++i) s += g_wovp[i][idx];
    g_wovgT[idx] = s * g[idx >> 8];
}

// ---------------------------------------------------------------------------
// k_fuse: single pass over c. One block = 8 pixels of one batch.
// ---------------------------------------------------------------------------
#define FUSE_SMEM (2048 * 12 * 4 + (64 * 3 + 256) * 4)
__global__ void __launch_bounds__(256, 2) k_fuse(const float* __restrict__ c) {
    extern __shared__ float sh[];
    float* cs   = sh;                 // [ (n*256+ch) * 12 + p ]
    float* dots = sh + 2048 * 12;     // [64] = [n*8+p]
    float* invs = dots + 64;
    float* wgt  = invs + 64;
    float* sg_s = wgt + 64;           // [256]

    int tid = threadIdx.x;
    int blk = blockIdx.x;
    int b = blk >> 9;
    int p0 = (blk & 511) * 8;

    sg_s[tid] = g_sg[b * C_DIM + tid];
    const float* cb = c + (size_t)b * N_TOK * C_DIM * HW;

    #pragma unroll
    for (int k = 0; k < 16; ++k) {
        int idx = tid + k * 256;
        int row = idx >> 1, f = idx & 1;
        float4 v = __ldg((const float4*)(cb + (size_t)row * HW + p0) + f);
        *(float4*)(cs + row * 12 + f * 4) = v;
    }
    __syncthreads();

    {
        int sub = tid & 3, pair = tid >> 2;
        int n = pair >> 3, p = pair & 7;
        float ss = 0.f, dt = 0.f;
        #pragma unroll 8
        for (int ch = sub; ch < C_DIM; ch += 4) {
            float v = cs[(n * C_DIM + ch) * 12 + p];
            ss += v * v;
            dt += v * sg_s[ch];
        }
        ss += __shfl_xor_sync(0xffffffffu, ss, 1);
        dt += __shfl_xor_sync(0xffffffffu, dt, 1);
        ss += __shfl_xor_sync(0xffffffffu, ss, 2);
        dt += __shfl_xor_sync(0xffffffffu, dt, 2);
        if (sub == 0) {
            float inv = rsqrtf(ss * (1.0f / C_DIM) + EPS);
            dots[pair] = dt * inv;
            invs[pair] = inv;
        }
    }
    __syncthreads();
    if (tid < 64) {
        int pp = tid & 7;
        float m = dots[pp];
        #pragma unroll
        for (int i = 1; i < N_TOK; ++i) m = fmaxf(m, dots[i * 8 + pp]);
        float sum = 0.f;
        #pragma unroll
        for (int i = 0; i < N_TOK; ++i) sum += __expf(dots[i * 8 + pp] - m);
        wgt[tid] = __expf(dots[tid] - m) / sum * invs[tid];
    }
    __syncthreads();

    {
        float4 a0 = make_float4(0.f, 0.f, 0.f, 0.f);
        float4 a1 = make_float4(0.f, 0.f, 0.f, 0.f);
        #pragma unroll
        for (int i = 0; i < N_TOK; ++i) {
            const float* r = cs + (i * C_DIM + tid) * 12;
            float4 v0 = *(const float4*)r;
            float4 v1 = *(const float4*)(r + 4);
            const float* w = wgt + i * 8;
            a0.x += w[0] * v0.x; a0.y += w[1] * v0.y; a0.z += w[2] * v0.z; a0.w += w[3] * v0.w;
            a1.x += w[4] * v1.x; a1.y += w[5] * v1.y; a1.z += w[6] * v1.z; a1.w += w[7] * v1.w;
        }
        float* ag = g_agg + (size_t)(b * C_DIM + tid) * HW + p0;
        *(float4*)ag = a0;
        *(float4*)(ag + 4) = a1;
    }
}

// ---------------------------------------------------------------------------
// k_gemm: out[b][co][p] = bo[co] + sum_ch WovgT[ch][co] * agg[b][ch][p]
// 64co x 128p tiles, K-chunks of 32, double-buffered smem, FFMA2 inner loop.
// ---------------------------------------------------------------------------
#define TP  128
#define TCO 64
#define KC  32
__global__ void __launch_bounds__(256) k_gemm(const float* __restrict__ bo,
                                              float* __restrict__ out) {
    __shared__ float aggS[2][KC][TP];                    // 32KB
    __shared__ unsigned long long wovD[2][KC][TCO];      // 32KB
    int tid = threadIdx.x;
    int blk = blockIdx.x;                  // 4b * 4ct * 32pt = 512
    int pt = blk & 31, ct = (blk >> 5) & 3, b = blk >> 7;
    int p0 = pt * TP, co0 = ct * TCO;
    int tx = tid & 31, ty = tid >> 5;
    int po = tx * 4, coo = ty * 8;

    unsigned long long acc[8][2];
    #pragma unroll
    for (int i = 0; i < 8; ++i) { acc[i][0] = 0ull; acc[i][1] = 0ull; }

    const float* aggB = g_agg + (size_t)b * C_DIM * HW + p0;

    // staging lambda (macro-style, inlined twice)
    #define STAGE(BUF, CH0) do {                                               \
        _Pragma("unroll")                                                      \
        for (int k = 0; k < 4; ++k) {                                          \
            int idx = tid + k * 256;                                           \
            int ch = idx >> 5, f = idx & 31;                                   \
            *(float4*)&aggS[BUF][ch][f * 4] =                                  \
                __ldg((const float4*)(aggB + (size_t)((CH0) + ch) * HW) + f);  \
        }                                                                      \
        _Pragma("unroll")                                                      \
        for (int k = 0; k < 8; ++k) {                                          \
            int idx = tid + k * 256;                                           \
            int ch = idx >> 6, co = idx & 63;                                  \
            float w = __ldg(&g_wovgT[((CH0) + ch) * C_DIM + co0 + co]);        \
            unsigned long long pk;                                             \
            asm("mov.b64 %0, {%1, %1};" : "=l"(pk) : "r"(__float_as_uint(w))); \
            wovD[BUF][ch][co] = pk;                                            \
        }                                                                      \
    } while (0)

    STAGE(0, 0);
    #pragma unroll
    for (int ck = 0; ck < 8; ++ck) {
        __syncthreads();
        if (ck < 7) STAGE((ck + 1) & 1, (ck + 1) * KC);
        int cur = ck & 1;
        #pragma unroll
        for (int ch = 0; ch < KC; ++ch) {
            ulonglong2 ap = *(const ulonglong2*)&aggS[cur][ch][po];
            const unsigned long long* wp = &wovD[cur][ch][coo];
            #pragma unroll
            for (int i = 0; i < 8; ++i) {
                FMA2(acc[i][0], wp[i], ap.x, acc[i][0]);
                FMA2(acc[i][1], wp[i], ap.y, acc[i][1]);
            }
        }
    }
    #undef STAGE

    float* ob = out + ((size_t)b * C_DIM + co0 + coo) * HW + p0 + po;
    #pragma unroll
    for (int i = 0; i < 8; ++i) {
        float bb = __ldg(&bo[co0 + coo + i]);
        unsigned lx, ly, hx, hy;
        asm("mov.b64 {%0, %1}, %2;" : "=r"(lx), "=r"(ly) : "l"(acc[i][0]));
        asm("mov.b64 {%0, %1}, %2;" : "=r"(hx), "=r"(hy) : "l"(acc[i][1]));
        float4 r = make_float4(__uint_as_float(lx) + bb, __uint_as_float(ly) + bb,
                               __uint_as_float(hx) + bb, __uint_as_float(hy) + bb);
        *(float4*)(ob + (size_t)i * HW) = r;
    }
}

extern "C" void kernel_launch(void* const* d_in, const int* in_sizes, int n_in,
                              void* d_out, int out_size) {
    const float* q   = (const float*)d_in[0];
    const float* c   = (const float*)d_in[1];
    const float* g   = (const float*)d_in[2];
    const float* Wq  = (const float*)d_in[3];
    const float* Wkv = (const float*)d_in[4];
    const float* Wo  = (const float*)d_in[5];
    const float* bo  = (const float*)d_in[6];
    float* out = (float*)d_out;

    cudaFuncSetAttribute(k_fuse, cudaFuncAttributeMaxDynamicSharedMemorySize, FUSE_SMEM);

    k_qp<<<dim3(B_SZ, 8), 256>>>(q, Wq);
    k_sgp<<<dim3(B_SZ, 8), 256>>>(Wkv);
    k_sgr<<<B_SZ, 256>>>(g);
    k_wovp<<<dim3(64, 8), 256>>>(Wo, Wkv);
    k_wovr<<<256, 256>>>(g);
    k_fuse<<<B_SZ * (HW / 8), 256, FUSE_SMEM>>>(c);
    k_gemm<<<512, 256>>>(bo, out);
}